// round 2
// baseline (speedup 1.0000x reference)
#include <cuda_runtime.h>

// Problem constants
#define N_TOK   9216        // H*W = 96*96
#define NBATCH  2
#define NC      64
#define NC8     8
#define QTILES  72          // 9216 / 128 query tiles
#define KTILES  144         // 9216 / 64 key tiles
#define NPAIR   72          // KTILES / 2

// ---------------- scratch (static device allocation: allowed) ----------------
__device__ float g_sig_inv[3];
__device__ float g_fT[NBATCH * N_TOK * NC8];   // keys,    [b][n][8]
__device__ float g_gT[NBATCH * N_TOK * NC8];   // queries, [b][n][8]
__device__ float g_hT[NBATCH * N_TOK * NC];    // values,  [b][n][64]

// ---------------- packed f32x2 helpers (sm_100+: FFMA2 path) ----------------
__device__ __forceinline__ unsigned long long pk2(float a, float b) {
    unsigned long long r;
    asm("mov.b64 %0, {%1, %2};" : "=l"(r) : "f"(a), "f"(b));
    return r;
}
__device__ __forceinline__ void upk2(unsigned long long v, float& a, float& b) {
    asm("mov.b64 {%0, %1}, %2;" : "=f"(a), "=f"(b) : "l"(v));
}
__device__ __forceinline__ void fma2(unsigned long long& d,
                                     unsigned long long a, unsigned long long b) {
    asm("fma.rn.f32x2 %0, %1, %2, %0;" : "+l"(d) : "l"(a), "l"(b));
}
__device__ __forceinline__ void mul2(unsigned long long& d, unsigned long long s) {
    asm("mul.rn.f32x2 %0, %0, %1;" : "+l"(d) : "l"(s));
}

// =============================================================================
// Kernel 1: spectral norms.  block 0: Wq (8x64), 1: Wk (8x64), 2: Wv (64x64).
// A = W W^T (SPD, r x r). Square twice (A^4), then 150 power iterations
// (effective exponent 600), Rayleigh quotient lam4 = v^T A^4 v, sigma = lam4^(1/8).
// =============================================================================
__global__ void sigma_kernel(const float* __restrict__ Wq,
                             const float* __restrict__ Wk,
                             const float* __restrict__ Wv) {
    __shared__ float A[64 * 64];
    __shared__ float A2[64 * 64];
    __shared__ float v[64];
    __shared__ float red[2];

    const int bid = blockIdx.x;
    const int t   = threadIdx.x;   // 64 threads

    const float* W;
    int r, c;
    if (bid == 0)      { W = Wq; r = NC8; c = NC; }
    else if (bid == 1) { W = Wk; r = NC8; c = NC; }
    else               { W = Wv; r = NC;  c = NC; }

    // Gram matrix A = W W^T  (row stride 64 in smem)
    for (int idx = t; idx < r * r; idx += 64) {
        int i = idx / r, j = idx % r;
        float acc = 0.f;
        for (int k = 0; k < c; k++) acc += W[i * c + k] * W[j * c + k];
        A[i * 64 + j] = acc;
    }
    __syncthreads();

    // A2 = A * A
    for (int i = t; i < r; i += 64)
        for (int j = 0; j < r; j++) {
            float acc = 0.f;
            for (int k = 0; k < r; k++) acc += A[i * 64 + k] * A[k * 64 + j];
            A2[i * 64 + j] = acc;
        }
    __syncthreads();
    // A = A2 * A2  (= gram^4)
    for (int i = t; i < r; i += 64)
        for (int j = 0; j < r; j++) {
            float acc = 0.f;
            for (int k = 0; k < r; k++) acc += A2[i * 64 + k] * A2[k * 64 + j];
            A[i * 64 + j] = acc;
        }

    if (t < r) v[t] = 1.0f;
    __syncthreads();

    for (int it = 0; it < 150; it++) {
        float wi = 0.f;
        if (t < r) {
            #pragma unroll 4
            for (int k = 0; k < r; k++) wi += A[t * 64 + k] * v[k];
        }
        float sq = (t < r) ? wi * wi : 0.f;
        #pragma unroll
        for (int off = 16; off > 0; off >>= 1)
            sq += __shfl_xor_sync(0xffffffffu, sq, off);
        if ((t & 31) == 0) red[t >> 5] = sq;
        __syncthreads();
        float inv = rsqrtf(red[0] + red[1]);
        if (t < r) v[t] = wi * inv;
        __syncthreads();
    }

    // Rayleigh quotient on A^4
    float wi = 0.f;
    if (t < r) {
        for (int k = 0; k < r; k++) wi += A[t * 64 + k] * v[k];
        wi *= v[t];
    }
    #pragma unroll
    for (int off = 16; off > 0; off >>= 1)
        wi += __shfl_xor_sync(0xffffffffu, wi, off);
    if ((t & 31) == 0) red[t >> 5] = wi;
    __syncthreads();
    if (t == 0) {
        float lam4 = red[0] + red[1];           // = sigma^8
        g_sig_inv[bid] = powf(lam4, -0.125f);   // 1/sigma
    }
}

// =============================================================================
// Kernel 2: projections.  f = (Wq/s) x + bq, g = (Wk/s) x + bk, h = (Wv/s) x + bv
// One thread per token n; outputs stored token-major for the attention kernel.
// grid = NBATCH*QTILES = 144 blocks, 128 threads.
// =============================================================================
__global__ void __launch_bounds__(128) proj_kernel(
    const float* __restrict__ x,
    const float* __restrict__ Wq, const float* __restrict__ bq,
    const float* __restrict__ Wk, const float* __restrict__ bk,
    const float* __restrict__ Wv, const float* __restrict__ bv) {

    __shared__ float Wvs[64 * 64];
    __shared__ float Wqs[8 * 64];
    __shared__ float Wks[8 * 64];
    __shared__ float bqs[8], bks[8], bvs[64];

    const int blk = blockIdx.x;
    const int b   = blk / QTILES;
    const int n0  = (blk % QTILES) * 128;
    const int t   = threadIdx.x;

    const float siq = g_sig_inv[0], sik = g_sig_inv[1], siv = g_sig_inv[2];
    for (int i = t; i < 64 * 64; i += 128) Wvs[i] = Wv[i] * siv;
    for (int i = t; i < 512; i += 128) { Wqs[i] = Wq[i] * siq; Wks[i] = Wk[i] * sik; }
    if (t < 8)  { bqs[t] = bq[t]; bks[t] = bk[t]; }
    if (t < 64) bvs[t] = bv[t];
    __syncthreads();

    const int n = n0 + t;
    // load my x column (coalesced across threads for each c)
    float xr[64];
    #pragma unroll
    for (int cc = 0; cc < 64; cc++)
        xr[cc] = x[((size_t)b * NC + cc) * N_TOK + n];

    float* fo = &g_fT[((size_t)b * N_TOK + n) * NC8];
    float* go = &g_gT[((size_t)b * N_TOK + n) * NC8];
    float* ho = &g_hT[((size_t)b * N_TOK + n) * NC];

    for (int o = 0; o < 8; o++) {
        float a1 = bqs[o], a2 = bks[o];
        #pragma unroll
        for (int cc = 0; cc < 64; cc++) {
            a1 += Wqs[o * 64 + cc] * xr[cc];
            a2 += Wks[o * 64 + cc] * xr[cc];
        }
        fo[o] = a1;
        go[o] = a2;
    }
    for (int o = 0; o < 64; o++) {
        float a1 = bvs[o];
        #pragma unroll
        for (int cc = 0; cc < 64; cc++) a1 += Wvs[o * 64 + cc] * xr[cc];
        ho[o] = a1;
    }
}

// =============================================================================
// Kernel 3: flash attention.
// scores[i,j] = f[:,i] . g[:,j], softmax over keys i per query j,
// out[c,j] = gamma * sum_i h[c,i] beta[i,j] / l_j + x[c,j].
// grid = 144 blocks (b, 128-query tile), 256 threads.
// thread t: query q = t&127, key-half = t>>7 (even/odd 64-key tiles).
// Packed f32x2 accumulators for the P*V loop; all smem tile reads are
// warp-uniform broadcasts (key/channel indices identical across lanes).
// =============================================================================
__global__ void __launch_bounds__(256, 1) attn_kernel(
    const float* __restrict__ x,
    const float* __restrict__ gamma,
    float* __restrict__ out) {

    // smem pool: [HS_A 1024 f4][HS_B 1024 f4][FS_A 128 f4][FS_B 128 f4]
    __shared__ float4 s_pool[2304];
    __shared__ float  mrg_m[128], mrg_l[128];
    float4* const HS_A = s_pool;
    float4* const HS_B = s_pool + 1024;
    float4* const FS_A = s_pool + 2048;
    float4* const FS_B = s_pool + 2176;

    const int blk  = blockIdx.x;
    const int b    = blk / QTILES;
    const int j0   = (blk % QTILES) * 128;
    const int t    = threadIdx.x;
    const int q    = t & 127;
    const int half = t >> 7;
    const int j    = j0 + q;

    // query vector (8 floats)
    const float4* gq = (const float4*)&g_gT[((size_t)b * N_TOK + j) * NC8];
    const float4 q0 = gq[0];
    const float4 q1 = gq[1];

    unsigned long long o2[32];           // 64 channels as 32 packed pairs
    #pragma unroll
    for (int i = 0; i < 32; i++) o2[i] = 0ull;
    float m = -1e30f, l = 0.f;

    const float4* fbase = (const float4*)&g_fT[(size_t)b * N_TOK * NC8];
    const float4* hbase = (const float4*)&g_hT[(size_t)b * N_TOK * NC];

    for (int it = 0; it < NPAIR; it++) {
        const int ke = it * 128;         // even tile first key
        const int ko = ke + 64;          // odd tile first key
        // cooperative tile load: h tiles 1024 f4 each, f tiles 128 f4 each
        #pragma unroll
        for (int v = t; v < 1024; v += 256) {
            HS_A[v] = hbase[ke * 16 + v];
            HS_B[v] = hbase[ko * 16 + v];
        }
        if (t < 128) FS_A[t] = fbase[ke * 2 + t];
        else         FS_B[t - 128] = fbase[ko * 2 + (t - 128)];
        if (t < 128) FS_A[t] = FS_A[t]; // (no-op; keep both halves symmetric)
        // second half of f tiles
        {
            int v2 = t + 256 - 256; (void)v2;
        }
        __syncthreads();
        // NOTE: f tiles are 128 f4 each; the two loads above cover both fully
        // (threads 0..127 -> FS_A[0..127], threads 128..255 -> FS_B[0..127]).

        const float4* fs = half ? FS_B : FS_A;
        const float4* hs = half ? HS_B : HS_A;

        for (int kc = 0; kc < 64; kc += 8) {
            float s[8];
            #pragma unroll
            for (int kk = 0; kk < 8; kk++) {
                float4 fa = fs[(kc + kk) * 2];
                float4 fb = fs[(kc + kk) * 2 + 1];
                s[kk] = fa.x * q0.x + fa.y * q0.y + fa.z * q0.z + fa.w * q0.w
                      + fb.x * q1.x + fb.y * q1.y + fb.z * q1.z + fb.w * q1.w;
            }
            float mt = s[0];
            #pragma unroll
            for (int kk = 1; kk < 8; kk++) mt = fmaxf(mt, s[kk]);
            if (mt > m) {                       // lazy rescale
                float sc = __expf(m - mt);
                l *= sc;
                unsigned long long sc2 = pk2(sc, sc);
                #pragma unroll
                for (int i = 0; i < 32; i++) mul2(o2[i], sc2);
                m = mt;
            }
            float p[8];
            float ls = 0.f;
            #pragma unroll
            for (int kk = 0; kk < 8; kk++) { p[kk] = __expf(s[kk] - m); ls += p[kk]; }
            l += ls;
            #pragma unroll
            for (int kk = 0; kk < 8; kk++) {
                unsigned long long pp = pk2(p[kk], p[kk]);
                const ulonglong2* hrow = (const ulonglong2*)(hs + (kc + kk) * 16);
                #pragma unroll
                for (int c4 = 0; c4 < 16; c4++) {
                    ulonglong2 hv = hrow[c4];
                    fma2(o2[c4 * 2],     hv.x, pp);
                    fma2(o2[c4 * 2 + 1], hv.y, pp);
                }
            }
        }
        __syncthreads();
    }

    // merge the two key-halves: half 1 publishes (m,l,o), half 0 combines + writes
    unsigned long long* mrg_o = (unsigned long long*)s_pool;  // 4096 u64 = 32KB
    if (half == 1) {
        mrg_m[q] = m;
        mrg_l[q] = l;
        #pragma unroll
        for (int i = 0; i < 32; i++) mrg_o[q * 32 + i] = o2[i];
    }
    __syncthreads();
    if (half == 0) {
        float m1 = mrg_m[q], l1 = mrg_l[q];
        float mn = fmaxf(m, m1);
        float s0 = __expf(m - mn);
        float s1 = __expf(m1 - mn);
        float L  = l * s0 + l1 * s1;
        float gscale = gamma[0] / L;

        const size_t base = (size_t)b * NC * N_TOK + j;
        const float* xp = x + base;
        float* op = out + base;
        #pragma unroll
        for (int i = 0; i < 32; i++) {
            float a0, a1, b0, b1;
            upk2(o2[i], a0, a1);
            upk2(mrg_o[q * 32 + i], b0, b1);
            int c0 = 2 * i, c1 = 2 * i + 1;
            op[(size_t)c0 * N_TOK] = (a0 * s0 + b0 * s1) * gscale + xp[(size_t)c0 * N_TOK];
            op[(size_t)c1 * N_TOK] = (a1 * s0 + b1 * s1) * gscale + xp[(size_t)c1 * N_TOK];
        }
    }
}

// =============================================================================
extern "C" void kernel_launch(void* const* d_in, const int* in_sizes, int n_in,
                              void* d_out, int out_size) {
    const float* x     = (const float*)d_in[0];
    const float* Wq    = (const float*)d_in[1];
    const float* bq    = (const float*)d_in[2];
    const float* Wk    = (const float*)d_in[3];
    const float* bk    = (const float*)d_in[4];
    const float* Wv    = (const float*)d_in[5];
    const float* bv    = (const float*)d_in[6];
    const float* gamma = (const float*)d_in[7];
    float* out = (float*)d_out;

    sigma_kernel<<<3, 64>>>(Wq, Wk, Wv);
    proj_kernel<<<NBATCH * QTILES, 128>>>(x, Wq, bq, Wk, bk, Wv, bv);
    attn_kernel<<<NBATCH * QTILES, 256>>>(x, gamma, out);
}

// round 4
// speedup vs baseline: 1.5914x; 1.5914x over previous
#include <cuda_runtime.h>

// Problem constants
#define N_TOK   9216        // H*W = 96*96
#define NBATCH  2
#define NC      64
#define NC8     8
#define QTILES  72          // 9216 / 128 query tiles

// ---------------- scratch (static device allocation: allowed) ----------------
__device__ float g_sig_inv[3];
__device__ float g_fT[NBATCH * N_TOK * NC8];   // keys,    [b][n][8]
__device__ float g_gT[NBATCH * N_TOK * NC8];   // queries, [b][n][8]
__device__ float g_hT[NBATCH * N_TOK * NC];    // values,  [b][n][64]

// ---------------- packed f32x2 helpers (sm_100+: FFMA2 path) ----------------
__device__ __forceinline__ unsigned long long pk2(float a, float b) {
    unsigned long long r;
    asm("mov.b64 %0, {%1, %2};" : "=l"(r) : "f"(a), "f"(b));
    return r;
}
__device__ __forceinline__ void upk2(unsigned long long v, float& a, float& b) {
    asm("mov.b64 {%0, %1}, %2;" : "=f"(a), "=f"(b) : "l"(v));
}
__device__ __forceinline__ void fma2(unsigned long long& d,
                                     unsigned long long a, unsigned long long b) {
    asm("fma.rn.f32x2 %0, %1, %2, %0;" : "+l"(d) : "l"(a), "l"(b));
}
__device__ __forceinline__ void mul2(unsigned long long& d, unsigned long long s) {
    asm("mul.rn.f32x2 %0, %0, %1;" : "+l"(d) : "l"(s));
}

// =============================================================================
// Kernel 1: spectral norms.  block 0: Wq (8x64), 1: Wk (8x64), 2: Wv (64x64).
// A = W W^T (SPD, r x r). Square 3x (A^8), 48 power iterations, Rayleigh
// quotient lam8 = v^T A^8 v, sigma = lam8^(1/16). 256 threads.
// =============================================================================
__global__ void __launch_bounds__(256) sigma_kernel(const float* __restrict__ Wq,
                                                    const float* __restrict__ Wk,
                                                    const float* __restrict__ Wv) {
    __shared__ float A[64 * 64];
    __shared__ float B[64 * 64];
    __shared__ float v[64];
    __shared__ float red[2];

    const int bid = blockIdx.x;
    const int t   = threadIdx.x;   // 256 threads

    const float* W;
    int r, c;
    if (bid == 0)      { W = Wq; r = NC8; c = NC; }
    else if (bid == 1) { W = Wk; r = NC8; c = NC; }
    else               { W = Wv; r = NC;  c = NC; }

    // Gram matrix A = W W^T  (row stride 64 in smem)
    for (int idx = t; idx < r * r; idx += 256) {
        int i = idx / r, j = idx % r;
        float acc = 0.f;
        #pragma unroll 4
        for (int k = 0; k < c; k++) acc += W[i * c + k] * W[j * c + k];
        A[i * 64 + j] = acc;
    }
    __syncthreads();

    // Three squarings: B = A*A; A = B*B; B = A*A.  Final A^8 lives in B.
    for (int sq = 0; sq < 3; sq++) {
        const float* src = (sq == 1) ? B : A;
        float*       dst = (sq == 1) ? A : B;
        for (int idx = t; idx < r * r; idx += 256) {
            int i = idx / r, j = idx % r;
            float a0 = 0.f, a1 = 0.f;
            for (int k = 0; k < r; k += 2) {
                a0 += src[i * 64 + k]     * src[k * 64 + j];
                a1 += src[i * 64 + k + 1] * src[(k + 1) * 64 + j];
            }
            dst[i * 64 + j] = a0 + a1;
        }
        __syncthreads();
    }

    if (t < r) v[t] = 1.0f;
    red[0] = 0.f; red[1] = 0.f;
    __syncthreads();

    for (int it = 0; it < 48; it++) {
        float wi = 0.f;
        if (t < r) {
            float w0 = 0.f, w1 = 0.f, w2 = 0.f, w3 = 0.f;
            for (int k = 0; k < r; k += 4) {
                w0 += B[t * 64 + k]     * v[k];
                w1 += B[t * 64 + k + 1] * v[k + 1];
                w2 += B[t * 64 + k + 2] * v[k + 2];
                w3 += B[t * 64 + k + 3] * v[k + 3];
            }
            wi = (w0 + w1) + (w2 + w3);
        }
        float sq = (t < 64) ? wi * wi : 0.f;
        #pragma unroll
        for (int off = 16; off > 0; off >>= 1)
            sq += __shfl_xor_sync(0xffffffffu, sq, off);
        if (t < 64 && (t & 31) == 0) red[t >> 5] = sq;
        __syncthreads();
        float inv = rsqrtf(red[0] + red[1]);
        if (t < r) v[t] = wi * inv;
        __syncthreads();
    }

    // Rayleigh quotient on A^8
    float wi = 0.f;
    if (t < r) {
        for (int k = 0; k < r; k++) wi += B[t * 64 + k] * v[k];
        wi *= v[t];
    }
    if (t >= 64) wi = 0.f;
    #pragma unroll
    for (int off = 16; off > 0; off >>= 1)
        wi += __shfl_xor_sync(0xffffffffu, wi, off);
    if (t < 64 && (t & 31) == 0) red[t >> 5] = wi;
    __syncthreads();
    if (t == 0) {
        float lam8 = red[0] + red[1];            // = sigma^16
        g_sig_inv[bid] = powf(lam8, -0.0625f);   // 1/sigma
    }
}

// =============================================================================
// Kernel 2: projections.  f = (Wq/s) x + bq, g = (Wk/s) x + bk, h = (Wv/s) x + bv
// One thread per token n; outputs stored token-major for the attention kernel.
// grid = 144 blocks, 128 threads.
// =============================================================================
__global__ void __launch_bounds__(128) proj_kernel(
    const float* __restrict__ x,
    const float* __restrict__ Wq, const float* __restrict__ bq,
    const float* __restrict__ Wk, const float* __restrict__ bk,
    const float* __restrict__ Wv, const float* __restrict__ bv) {

    __shared__ float Wvs[64 * 64];
    __shared__ float Wqs[8 * 64];
    __shared__ float Wks[8 * 64];
    __shared__ float bqs[8], bks[8], bvs[64];

    const int blk = blockIdx.x;
    const int b   = blk / QTILES;
    const int n0  = (blk % QTILES) * 128;
    const int t   = threadIdx.x;

    const float siq = g_sig_inv[0], sik = g_sig_inv[1], siv = g_sig_inv[2];
    for (int i = t; i < 64 * 64; i += 128) Wvs[i] = Wv[i] * siv;
    for (int i = t; i < 512; i += 128) { Wqs[i] = Wq[i] * siq; Wks[i] = Wk[i] * sik; }
    if (t < 8)  { bqs[t] = bq[t]; bks[t] = bk[t]; }
    if (t < 64) bvs[t] = bv[t];
    __syncthreads();

    const int n = n0 + t;
    float xr[64];
    #pragma unroll
    for (int cc = 0; cc < 64; cc++)
        xr[cc] = x[((size_t)b * NC + cc) * N_TOK + n];

    float* fo = &g_fT[((size_t)b * N_TOK + n) * NC8];
    float* go = &g_gT[((size_t)b * N_TOK + n) * NC8];
    float* ho = &g_hT[((size_t)b * N_TOK + n) * NC];

    for (int o = 0; o < 8; o++) {
        float a1 = bqs[o], a2 = bks[o];
        #pragma unroll
        for (int cc = 0; cc < 64; cc++) {
            a1 += Wqs[o * 64 + cc] * xr[cc];
            a2 += Wks[o * 64 + cc] * xr[cc];
        }
        fo[o] = a1;
        go[o] = a2;
    }
    for (int o = 0; o < 64; o++) {
        float a1 = bvs[o];
        #pragma unroll
        for (int cc = 0; cc < 64; cc++) a1 += Wvs[o * 64 + cc] * xr[cc];
        ho[o] = a1;
    }
}

// =============================================================================
// Kernel 3: flash attention, 2 queries/thread, 4-way key split.
// grid = 144 blocks (b, 128-query tile), 256 threads.
// thread t: query pair qp = t&63 (queries j0+2qp, j0+2qp+1), quarter = t>>6
// (32-key slice of the current 128-key tile).
// h-row smem loads amortized over 2 queries -> FMA:LDS = 4:1.
// =============================================================================
__global__ void __launch_bounds__(256, 1) attn_kernel(
    const float* __restrict__ x,
    const float* __restrict__ gamma,
    float* __restrict__ out) {

    // smem pool: HS = 128 keys x 16 f4 (32KB), FS = 128 keys x 2 f4 (4KB)
    __shared__ float4 s_pool[2304];
    __shared__ float  mrg_m[128], mrg_l[128];
    float4* const HS = s_pool;
    float4* const FS = s_pool + 2048;

    const int blk     = blockIdx.x;
    const int b       = blk / QTILES;
    const int j0      = (blk % QTILES) * 128;
    const int t       = threadIdx.x;
    const int qp      = t & 63;
    const int quarter = t >> 6;
    const int jA      = j0 + qp * 2;

    const float4* gA = (const float4*)&g_gT[((size_t)b * N_TOK + jA) * NC8];
    const float4 qa0 = gA[0], qa1 = gA[1];
    const float4 qb0 = gA[2], qb1 = gA[3];   // query jA+1 is adjacent

    unsigned long long oA[32], oB[32];
    #pragma unroll
    for (int i = 0; i < 32; i++) { oA[i] = 0ull; oB[i] = 0ull; }
    float ma = -1e30f, la = 0.f, mb = -1e30f, lb = 0.f;

    const float4* fbase = (const float4*)&g_fT[(size_t)b * N_TOK * NC8];
    const float4* hbase = (const float4*)&g_hT[(size_t)b * N_TOK * NC];

    for (int it = 0; it < QTILES; it++) {
        const int k0 = it * 128;
        #pragma unroll
        for (int w = 0; w < 8; w++)
            HS[t + 256 * w] = hbase[k0 * 16 + t + 256 * w];
        FS[t] = fbase[k0 * 2 + t];
        __syncthreads();

        const int r0 = quarter * 32;
        for (int kc = 0; kc < 32; kc += 8) {
            float pA[8], pB[8];
            {
                float sA[8], sB[8];
                #pragma unroll
                for (int kk = 0; kk < 8; kk++) {
                    float4 fa = FS[(r0 + kc + kk) * 2];
                    float4 fb = FS[(r0 + kc + kk) * 2 + 1];
                    sA[kk] = fa.x * qa0.x + fa.y * qa0.y + fa.z * qa0.z + fa.w * qa0.w
                           + fb.x * qa1.x + fb.y * qa1.y + fb.z * qa1.z + fb.w * qa1.w;
                    sB[kk] = fa.x * qb0.x + fa.y * qb0.y + fa.z * qb0.z + fa.w * qb0.w
                           + fb.x * qb1.x + fb.y * qb1.y + fb.z * qb1.z + fb.w * qb1.w;
                }
                float mtA = sA[0], mtB = sB[0];
                #pragma unroll
                for (int kk = 1; kk < 8; kk++) {
                    mtA = fmaxf(mtA, sA[kk]);
                    mtB = fmaxf(mtB, sB[kk]);
                }
                if (mtA > ma) {
                    float sc = __expf(ma - mtA);
                    la *= sc;
                    unsigned long long sc2 = pk2(sc, sc);
                    #pragma unroll
                    for (int i = 0; i < 32; i++) mul2(oA[i], sc2);
                    ma = mtA;
                }
                if (mtB > mb) {
                    float sc = __expf(mb - mtB);
                    lb *= sc;
                    unsigned long long sc2 = pk2(sc, sc);
                    #pragma unroll
                    for (int i = 0; i < 32; i++) mul2(oB[i], sc2);
                    mb = mtB;
                }
                float lsA = 0.f, lsB = 0.f;
                #pragma unroll
                for (int kk = 0; kk < 8; kk++) {
                    pA[kk] = __expf(sA[kk] - ma); lsA += pA[kk];
                    pB[kk] = __expf(sB[kk] - mb); lsB += pB[kk];
                }
                la += lsA; lb += lsB;
            }
            #pragma unroll
            for (int kk = 0; kk < 8; kk++) {
                unsigned long long ppA = pk2(pA[kk], pA[kk]);
                unsigned long long ppB = pk2(pB[kk], pB[kk]);
                const ulonglong2* hrow = (const ulonglong2*)(HS + (r0 + kc + kk) * 16);
                #pragma unroll
                for (int c4 = 0; c4 < 16; c4++) {
                    ulonglong2 hv = hrow[c4];
                    fma2(oA[c4 * 2],     hv.x, ppA);
                    fma2(oA[c4 * 2 + 1], hv.y, ppA);
                    fma2(oB[c4 * 2],     hv.x, ppB);
                    fma2(oB[c4 * 2 + 1], hv.y, ppB);
                }
            }
        }
        __syncthreads();
    }

    // merge quarters 1..3 into quarter 0 (3 sequential smem rounds)
    unsigned long long* mo = (unsigned long long*)s_pool;   // 128q x 32 u64 = 32KB
    for (int round = 1; round < 4; round++) {
        __syncthreads();
        if (quarter == round) {
            mrg_m[qp * 2]     = ma; mrg_l[qp * 2]     = la;
            mrg_m[qp * 2 + 1] = mb; mrg_l[qp * 2 + 1] = lb;
            #pragma unroll
            for (int i = 0; i < 32; i++) {
                mo[(qp * 2) * 32 + i]     = oA[i];
                mo[(qp * 2 + 1) * 32 + i] = oB[i];
            }
        }
        __syncthreads();
        if (quarter == 0) {
            // query A
            {
                float m1 = mrg_m[qp * 2], l1 = mrg_l[qp * 2];
                float mn = fmaxf(ma, m1);
                float s0 = __expf(ma - mn), s1 = __expf(m1 - mn);
                la = la * s0 + l1 * s1;
                ma = mn;
                unsigned long long s02 = pk2(s0, s0), s12 = pk2(s1, s1);
                #pragma unroll
                for (int i = 0; i < 32; i++) {
                    mul2(oA[i], s02);
                    fma2(oA[i], mo[(qp * 2) * 32 + i], s12);
                }
            }
            // query B
            {
                float m1 = mrg_m[qp * 2 + 1], l1 = mrg_l[qp * 2 + 1];
                float mn = fmaxf(mb, m1);
                float s0 = __expf(mb - mn), s1 = __expf(m1 - mn);
                lb = lb * s0 + l1 * s1;
                mb = mn;
                unsigned long long s02 = pk2(s0, s0), s12 = pk2(s1, s1);
                #pragma unroll
                for (int i = 0; i < 32; i++) {
                    mul2(oB[i], s02);
                    fma2(oB[i], mo[(qp * 2 + 1) * 32 + i], s12);
                }
            }
        }
    }
    __syncthreads();

    if (quarter == 0) {
        const float ga  = gamma[0];
        const float gsA = ga / la, gsB = ga / lb;
        const size_t base = (size_t)b * NC * N_TOK + jA;
        const float* xp = x + base;
        float* op = out + base;
        #pragma unroll
        for (int i = 0; i < 32; i++) {
            float a0, a1, b0, b1;
            upk2(oA[i], a0, a1);
            upk2(oB[i], b0, b1);
            const size_t c0 = (size_t)(2 * i) * N_TOK;
            const size_t c1 = c0 + N_TOK;
            op[c0]     = a0 * gsA + xp[c0];
            op[c0 + 1] = b0 * gsB + xp[c0 + 1];
            op[c1]     = a1 * gsA + xp[c1];
            op[c1 + 1] = b1 * gsB + xp[c1 + 1];
        }
    }
}

// =============================================================================
extern "C" void kernel_launch(void* const* d_in, const int* in_sizes, int n_in,
                              void* d_out, int out_size) {
    const float* x     = (const float*)d_in[0];
    const float* Wq    = (const float*)d_in[1];
    const float* bq    = (const float*)d_in[2];
    const float* Wk    = (const float*)d_in[3];
    const float* bk    = (const float*)d_in[4];
    const float* Wv    = (const float*)d_in[5];
    const float* bv    = (const float*)d_in[6];
    const float* gamma = (const float*)d_in[7];
    float* out = (float*)d_out;

    sigma_kernel<<<3, 256>>>(Wq, Wk, Wv);
    proj_kernel<<<NBATCH * QTILES, 128>>>(x, Wq, bq, Wk, bk, Wv, bv);
    attn_kernel<<<NBATCH * QTILES, 256>>>(x, gamma, out);
}

// round 5
// speedup vs baseline: 2.1047x; 1.3226x over previous
#include <cuda_runtime.h>

// Problem constants
#define N_TOK   9216        // H*W = 96*96
#define NBATCH  2
#define NC      64
#define NC8     8
#define QTILES  72          // 9216 / 128 query tiles
#define KTILE   64
#define NKT     144         // 9216 / 64 key tiles

// ---------------- scratch (static device allocation: allowed) ----------------
__device__ float g_sig_inv[3];
__device__ float g_fT[NBATCH * N_TOK * NC8];   // keys,    [b][n][8]
__device__ float g_gT[NBATCH * N_TOK * NC8];   // queries, [b][n][8]
__device__ float g_hT[NBATCH * N_TOK * NC];    // values,  [b][n][64]

// ---------------- packed f32x2 helpers (sm_100+: FFMA2 path) ----------------
__device__ __forceinline__ unsigned long long pk2(float a, float b) {
    unsigned long long r;
    asm("mov.b64 %0, {%1, %2};" : "=l"(r) : "f"(a), "f"(b));
    return r;
}
__device__ __forceinline__ void upk2(unsigned long long v, float& a, float& b) {
    asm("mov.b64 {%0, %1}, %2;" : "=f"(a), "=f"(b) : "l"(v));
}
__device__ __forceinline__ void fma2(unsigned long long& d,
                                     unsigned long long a, unsigned long long b) {
    asm("fma.rn.f32x2 %0, %1, %2, %0;" : "+l"(d) : "l"(a), "l"(b));
}
__device__ __forceinline__ void mul2(unsigned long long& d, unsigned long long s) {
    asm("mul.rn.f32x2 %0, %0, %1;" : "+l"(d) : "l"(s));
}

// =============================================================================
// Kernel 1: spectral norms via trace-normalized repeated squaring.
// P_0 = W W^T; P_{k+1} = (P_k / t_k)^2, t_k = trace(P_k), k = 0..4.
// Then 12 power iterations + Rayleigh on P_5 (~A^32 normalized), unwind:
// lam_k = t_k * sqrt(lam_{k+1});  sigma = sqrt(lam_0).
// Template specialization -> fully unrolled loops. 256 threads, 3 blocks.
// =============================================================================
template<int R, int C>
__device__ __forceinline__ void sigma_body(const float* __restrict__ W,
                                           float* A, float* Bm, float* v,
                                           float* sT, float* red, int outIdx) {
    const int t = threadIdx.x;   // 256

    // Gram: A = W W^T (row stride 64)
    for (int idx = t; idx < R * R; idx += 256) {
        int i = idx / R, j = idx % R;
        float a0 = 0.f, a1 = 0.f, a2 = 0.f, a3 = 0.f;
        #pragma unroll
        for (int k = 0; k < C; k += 4) {
            a0 += W[i * C + k]     * W[j * C + k];
            a1 += W[i * C + k + 1] * W[j * C + k + 1];
            a2 += W[i * C + k + 2] * W[j * C + k + 2];
            a3 += W[i * C + k + 3] * W[j * C + k + 3];
        }
        A[i * 64 + j] = (a0 + a1) + (a2 + a3);
    }
    __syncthreads();
    // trace(P_0)
    if (t < 32) {
        float s = 0.f;
        for (int k = t; k < R; k += 32) s += A[k * 64 + k];
        #pragma unroll
        for (int o = 16; o > 0; o >>= 1) s += __shfl_xor_sync(0xffffffffu, s, o);
        if (t == 0) sT[0] = s;
    }
    __syncthreads();

    // 5 squarings with fused normalization
    float* src = A;
    float* dst = Bm;
    #pragma unroll
    for (int sq = 0; sq < 5; sq++) {
        const float invt = 1.0f / sT[sq];
        const float f = invt * invt;
        for (int idx = t; idx < R * R; idx += 256) {
            int i = idx / R, j = idx % R;
            float a0 = 0.f, a1 = 0.f, a2 = 0.f, a3 = 0.f;
            #pragma unroll
            for (int k = 0; k < R; k += 4) {
                a0 += src[i * 64 + k]     * src[k * 64 + j];
                a1 += src[i * 64 + k + 1] * src[(k + 1) * 64 + j];
                a2 += src[i * 64 + k + 2] * src[(k + 2) * 64 + j];
                a3 += src[i * 64 + k + 3] * src[(k + 3) * 64 + j];
            }
            dst[i * 64 + j] = ((a0 + a1) + (a2 + a3)) * f;
        }
        __syncthreads();
        if (t < 32) {
            float s = 0.f;
            for (int k = t; k < R; k += 32) s += dst[k * 64 + k];
            #pragma unroll
            for (int o = 16; o > 0; o >>= 1) s += __shfl_xor_sync(0xffffffffu, s, o);
            if (t == 0) sT[sq + 1] = s;
        }
        __syncthreads();
        float* tmp = src; src = dst; dst = tmp;
    }
    // P_5 now in src.

    if (t < R) v[t] = 1.0f;
    __syncthreads();

    #pragma unroll 1
    for (int it = 0; it < 12; it++) {
        float wi = 0.f;
        if (t < R) {
            float w0 = 0.f, w1 = 0.f, w2 = 0.f, w3 = 0.f;
            #pragma unroll
            for (int k = 0; k < R; k += 4) {
                w0 += src[t * 64 + k]     * v[k];
                w1 += src[t * 64 + k + 1] * v[k + 1];
                w2 += src[t * 64 + k + 2] * v[k + 2];
                w3 += src[t * 64 + k + 3] * v[k + 3];
            }
            wi = (w0 + w1) + (w2 + w3);
        }
        float s2 = (t < 64) ? wi * wi : 0.f;
        #pragma unroll
        for (int o = 16; o > 0; o >>= 1) s2 += __shfl_xor_sync(0xffffffffu, s2, o);
        if (t < 64 && (t & 31) == 0) red[t >> 5] = s2;
        __syncthreads();
        float inv = rsqrtf(red[0] + red[1]);
        if (t < R) v[t] = wi * inv;
        __syncthreads();
    }

    // Rayleigh quotient mu = v^T P_5 v (v unit)
    float wi = 0.f;
    if (t < R) {
        #pragma unroll
        for (int k = 0; k < R; k++) wi += src[t * 64 + k] * v[k];
        wi *= v[t];
    }
    if (t >= 64) wi = 0.f;
    #pragma unroll
    for (int o = 16; o > 0; o >>= 1) wi += __shfl_xor_sync(0xffffffffu, wi, o);
    if (t < 64 && (t & 31) == 0) red[t >> 5] = wi;
    __syncthreads();
    if (t == 0) {
        float mu = red[0] + red[1];              // lam(P_5)
        #pragma unroll
        for (int k = 4; k >= 0; k--) mu = sT[k] * sqrtf(mu);
        g_sig_inv[outIdx] = rsqrtf(mu);          // 1/sigma = lam(A)^(-1/2)
    }
}

__global__ void __launch_bounds__(256) sigma_kernel(const float* __restrict__ Wq,
                                                    const float* __restrict__ Wk,
                                                    const float* __restrict__ Wv) {
    __shared__ float A[64 * 64];
    __shared__ float Bm[64 * 64];
    __shared__ float v[64];
    __shared__ float sT[8];
    __shared__ float red[2];

    if (blockIdx.x == 0)      sigma_body<NC8, NC>(Wq, A, Bm, v, sT, red, 0);
    else if (blockIdx.x == 1) sigma_body<NC8, NC>(Wk, A, Bm, v, sT, red, 1);
    else                      sigma_body<NC,  NC>(Wv, A, Bm, v, sT, red, 2);
}

// =============================================================================
// Kernel 2: projections (unchanged).
// =============================================================================
__global__ void __launch_bounds__(128) proj_kernel(
    const float* __restrict__ x,
    const float* __restrict__ Wq, const float* __restrict__ bq,
    const float* __restrict__ Wk, const float* __restrict__ bk,
    const float* __restrict__ Wv, const float* __restrict__ bv) {

    __shared__ float Wvs[64 * 64];
    __shared__ float Wqs[8 * 64];
    __shared__ float Wks[8 * 64];
    __shared__ float bqs[8], bks[8], bvs[64];

    const int blk = blockIdx.x;
    const int b   = blk / QTILES;
    const int n0  = (blk % QTILES) * 128;
    const int t   = threadIdx.x;

    const float siq = g_sig_inv[0], sik = g_sig_inv[1], siv = g_sig_inv[2];
    for (int i = t; i < 64 * 64; i += 128) Wvs[i] = Wv[i] * siv;
    for (int i = t; i < 512; i += 128) { Wqs[i] = Wq[i] * siq; Wks[i] = Wk[i] * sik; }
    if (t < 8)  { bqs[t] = bq[t]; bks[t] = bk[t]; }
    if (t < 64) bvs[t] = bv[t];
    __syncthreads();

    const int n = n0 + t;
    float xr[64];
    #pragma unroll
    for (int cc = 0; cc < 64; cc++)
        xr[cc] = x[((size_t)b * NC + cc) * N_TOK + n];

    float* fo = &g_fT[((size_t)b * N_TOK + n) * NC8];
    float* go = &g_gT[((size_t)b * N_TOK + n) * NC8];
    float* ho = &g_hT[((size_t)b * N_TOK + n) * NC];

    for (int o = 0; o < 8; o++) {
        float a1 = bqs[o], a2 = bks[o];
        #pragma unroll
        for (int cc = 0; cc < 64; cc++) {
            a1 += Wqs[o * 64 + cc] * xr[cc];
            a2 += Wks[o * 64 + cc] * xr[cc];
        }
        fo[o] = a1;
        go[o] = a2;
    }
    for (int o = 0; o < 64; o++) {
        float a1 = bvs[o];
        #pragma unroll
        for (int cc = 0; cc < 64; cc++) a1 += Wvs[o * 64 + cc] * xr[cc];
        ho[o] = a1;
    }
}

// =============================================================================
// Kernel 3: flash attention, 2 queries/thread, 4-way key split,
// 64-key tiles, double-buffered smem with register prefetch:
// [STS cur][bar][LDG next][compute cur] -> one barrier per tile, load latency
// hidden under ~1024 FFMA2 of compute.
// grid = 144 blocks (b, 128-query tile), 256 threads.
// =============================================================================
__global__ void __launch_bounds__(256, 1) attn_kernel(
    const float* __restrict__ x,
    const float* __restrict__ gamma,
    float* __restrict__ out) {

    // pool layout (f4): [HS0 1024][FS0 128][HS1 1024][FS1 128] = 2304 f4 (36.8KB)
    __shared__ float4 s_pool[2304];
    __shared__ float  mrg_m[128], mrg_l[128];

    const int blk     = blockIdx.x;
    const int b       = blk / QTILES;
    const int j0      = (blk % QTILES) * 128;
    const int t       = threadIdx.x;
    const int qp      = t & 63;
    const int quarter = t >> 6;
    const int jA      = j0 + qp * 2;

    const float4* gA = (const float4*)&g_gT[((size_t)b * N_TOK + jA) * NC8];
    const float4 qa0 = gA[0], qa1 = gA[1];
    const float4 qb0 = gA[2], qb1 = gA[3];

    unsigned long long oA[32], oB[32];
    #pragma unroll
    for (int i = 0; i < 32; i++) { oA[i] = 0ull; oB[i] = 0ull; }
    float ma = -1e30f, la = 0.f, mb = -1e30f, lb = 0.f;

    const float4* fbase = (const float4*)&g_fT[(size_t)b * N_TOK * NC8];
    const float4* hbase = (const float4*)&g_hT[(size_t)b * N_TOK * NC];

    // prefetch tile 0
    float4 hp0 = hbase[t];
    float4 hp1 = hbase[t + 256];
    float4 hp2 = hbase[t + 512];
    float4 hp3 = hbase[t + 768];
    float4 fp;
    if (t < 128) fp = fbase[t];

    for (int it = 0; it < NKT; it++) {
        float4* const HS = s_pool + (it & 1) * 1152;
        float4* const FS = HS + 1024;
        HS[t]       = hp0;
        HS[t + 256] = hp1;
        HS[t + 512] = hp2;
        HS[t + 768] = hp3;
        if (t < 128) FS[t] = fp;
        __syncthreads();
        if (it + 1 < NKT) {
            const int nb = (it + 1) * 1024;
            hp0 = hbase[nb + t];
            hp1 = hbase[nb + t + 256];
            hp2 = hbase[nb + t + 512];
            hp3 = hbase[nb + t + 768];
            if (t < 128) fp = fbase[(it + 1) * 128 + t];
        }

        const int r0 = quarter * 16;
        #pragma unroll
        for (int kc = 0; kc < 16; kc += 8) {
            float pA[8], pB[8];
            {
                float sA[8], sB[8];
                #pragma unroll
                for (int kk = 0; kk < 8; kk++) {
                    float4 fa = FS[(r0 + kc + kk) * 2];
                    float4 fb = FS[(r0 + kc + kk) * 2 + 1];
                    sA[kk] = fa.x * qa0.x + fa.y * qa0.y + fa.z * qa0.z + fa.w * qa0.w
                           + fb.x * qa1.x + fb.y * qa1.y + fb.z * qa1.z + fb.w * qa1.w;
                    sB[kk] = fa.x * qb0.x + fa.y * qb0.y + fa.z * qb0.z + fa.w * qb0.w
                           + fb.x * qb1.x + fb.y * qb1.y + fb.z * qb1.z + fb.w * qb1.w;
                }
                float mtA = sA[0], mtB = sB[0];
                #pragma unroll
                for (int kk = 1; kk < 8; kk++) {
                    mtA = fmaxf(mtA, sA[kk]);
                    mtB = fmaxf(mtB, sB[kk]);
                }
                if (mtA > ma) {
                    float sc = __expf(ma - mtA);
                    la *= sc;
                    unsigned long long sc2 = pk2(sc, sc);
                    #pragma unroll
                    for (int i = 0; i < 32; i++) mul2(oA[i], sc2);
                    ma = mtA;
                }
                if (mtB > mb) {
                    float sc = __expf(mb - mtB);
                    lb *= sc;
                    unsigned long long sc2 = pk2(sc, sc);
                    #pragma unroll
                    for (int i = 0; i < 32; i++) mul2(oB[i], sc2);
                    mb = mtB;
                }
                float lsA = 0.f, lsB = 0.f;
                #pragma unroll
                for (int kk = 0; kk < 8; kk++) {
                    pA[kk] = __expf(sA[kk] - ma); lsA += pA[kk];
                    pB[kk] = __expf(sB[kk] - mb); lsB += pB[kk];
                }
                la += lsA; lb += lsB;
            }
            #pragma unroll
            for (int kk = 0; kk < 8; kk++) {
                unsigned long long ppA = pk2(pA[kk], pA[kk]);
                unsigned long long ppB = pk2(pB[kk], pB[kk]);
                const ulonglong2* hrow = (const ulonglong2*)(HS + (r0 + kc + kk) * 16);
                #pragma unroll
                for (int c4 = 0; c4 < 16; c4++) {
                    ulonglong2 hv = hrow[c4];
                    fma2(oA[c4 * 2],     hv.x, ppA);
                    fma2(oA[c4 * 2 + 1], hv.y, ppA);
                    fma2(oB[c4 * 2],     hv.x, ppB);
                    fma2(oB[c4 * 2 + 1], hv.y, ppB);
                }
            }
        }
    }

    // merge quarters 1..3 into quarter 0 (3 sequential smem rounds)
    unsigned long long* mo = (unsigned long long*)s_pool;   // 128q x 32 u64 = 32KB
    for (int round = 1; round < 4; round++) {
        __syncthreads();
        if (quarter == round) {
            mrg_m[qp * 2]     = ma; mrg_l[qp * 2]     = la;
            mrg_m[qp * 2 + 1] = mb; mrg_l[qp * 2 + 1] = lb;
            #pragma unroll
            for (int i = 0; i < 32; i++) {
                mo[(qp * 2) * 32 + i]     = oA[i];
                mo[(qp * 2 + 1) * 32 + i] = oB[i];
            }
        }
        __syncthreads();
        if (quarter == 0) {
            {
                float m1 = mrg_m[qp * 2], l1 = mrg_l[qp * 2];
                float mn = fmaxf(ma, m1);
                float s0 = __expf(ma - mn), s1 = __expf(m1 - mn);
                la = la * s0 + l1 * s1;
                ma = mn;
                unsigned long long s02 = pk2(s0, s0), s12 = pk2(s1, s1);
                #pragma unroll
                for (int i = 0; i < 32; i++) {
                    mul2(oA[i], s02);
                    fma2(oA[i], mo[(qp * 2) * 32 + i], s12);
                }
            }
            {
                float m1 = mrg_m[qp * 2 + 1], l1 = mrg_l[qp * 2 + 1];
                float mn = fmaxf(mb, m1);
                float s0 = __expf(mb - mn), s1 = __expf(m1 - mn);
                lb = lb * s0 + l1 * s1;
                mb = mn;
                unsigned long long s02 = pk2(s0, s0), s12 = pk2(s1, s1);
                #pragma unroll
                for (int i = 0; i < 32; i++) {
                    mul2(oB[i], s02);
                    fma2(oB[i], mo[(qp * 2 + 1) * 32 + i], s12);
                }
            }
        }
    }
    __syncthreads();

    if (quarter == 0) {
        const float ga  = gamma[0];
        const float gsA = ga / la, gsB = ga / lb;
        const size_t base = (size_t)b * NC * N_TOK + jA;
        const float* xp = x + base;
        float* op = out + base;
        #pragma unroll
        for (int i = 0; i < 32; i++) {
            float a0, a1, b0, b1;
            upk2(oA[i], a0, a1);
            upk2(oB[i], b0, b1);
            const size_t c0 = (size_t)(2 * i) * N_TOK;
            const size_t c1 = c0 + N_TOK;
            op[c0]     = a0 * gsA + xp[c0];
            op[c0 + 1] = b0 * gsB + xp[c0 + 1];
            op[c1]     = a1 * gsA + xp[c1];
            op[c1 + 1] = b1 * gsB + xp[c1 + 1];
        }
    }
}

// =============================================================================
extern "C" void kernel_launch(void* const* d_in, const int* in_sizes, int n_in,
                              void* d_out, int out_size) {
    const float* x     = (const float*)d_in[0];
    const float* Wq    = (const float*)d_in[1];
    const float* bq    = (const float*)d_in[2];
    const float* Wk    = (const float*)d_in[3];
    const float* bk    = (const float*)d_in[4];
    const float* Wv    = (const float*)d_in[5];
    const float* bv    = (const float*)d_in[6];
    const float* gamma = (const float*)d_in[7];
    float* out = (float*)d_out;

    sigma_kernel<<<3, 256>>>(Wq, Wk, Wv);
    proj_kernel<<<NBATCH * QTILES, 128>>>(x, Wq, bq, Wk, bk, Wv, bv);
    attn_kernel<<<NBATCH * QTILES, 256>>>(x, gamma, out);
}